// round 1
// baseline (speedup 1.0000x reference)
#include <cuda_runtime.h>
#include <cstdint>

#define BB 64
#define LL 1024
#define SS 8
#define DD 128
#define BL (BB*LL)          // 65536
#define NELEM (2*BL)        // 131072 element-sides
#define NK (DD+1)           // 129 relu-interval table rows
#define KEYSPACE 32768      // id*8 + (snap-1), id < 4096

// ---- device scratch (no allocations allowed) ----
__device__ float  g_sortedT[DD];
__device__ int    g_rank[DD];
__device__ float  g_P[NK*DD];
__device__ float  g_Q[NK*DD];
__device__ float2 g_cnt[NELEM];   // (self*valid, cross*valid) per element-side

// ============================================================
// Prologue 1: sort enc relu breakpoints t_d = -b1[d]/w1[d]
// ============================================================
__global__ void k_prep_sort(const float* __restrict__ ew1,
                            const float* __restrict__ eb1) {
    __shared__ float t[DD];
    int d = threadIdx.x;
    float w = ew1[d], b = eb1[d];
    float td = (w != 0.0f) ? (-b / w) : __int_as_float(0x7f800000); // +inf
    t[d] = td;
    __syncthreads();
    int r = 0;
    for (int j = 0; j < DD; ++j) {
        float tj = t[j];
        r += (tj < td || (tj == td && j < d)) ? 1 : 0;
    }
    g_rank[d] = r;
    g_sortedT[r] = td;
}

// ============================================================
// Prologue 2: per-interval prefix tables
//   P[k][d'] = sum_{d active in interval k} w1[d]*w2[d][d']
//   Q[k][d'] = sum_{d active in interval k} b1[d]*w2[d][d']
// active(d,k): w1>0 -> rank[d]<k ; w1<0 -> rank[d]>=k ; w1==0 -> b1>0
// ============================================================
__global__ void k_prep_table(const float* __restrict__ ew1,
                             const float* __restrict__ eb1,
                             const float* __restrict__ ew2) {
    __shared__ float sw[DD], sb[DD];
    __shared__ int   sr[DD];
    int k = blockIdx.x, dp = threadIdx.x;
    sw[dp] = ew1[dp];
    sb[dp] = eb1[dp];
    sr[dp] = g_rank[dp];
    __syncthreads();
    float p = 0.f, q = 0.f;
    for (int d = 0; d < DD; ++d) {
        float w = sw[d], b = sb[d];
        int   r = sr[d];
        bool act = (w > 0.f) ? (r < k) : ((w < 0.f) ? (r >= k) : (b > 0.f));
        if (act) {
            float w2 = ew2[d*DD + dp];
            p = fmaf(w, w2, p);
            q = fmaf(b, w2, q);
        }
    }
    g_P[k*DD + dp] = p;
    g_Q[k*DD + dp] = q;
}

// ============================================================
// Count kernel: per-batch smem histogram of packed (id,snap) keys,
// then per-position self/cross lookups. Packed 2x u16 counters per u32.
// ============================================================
__global__ void k_count(const int* __restrict__ sid, const int* __restrict__ did,
                        const int* __restrict__ ssn, const int* __restrict__ dsn) {
    extern __shared__ uint32_t tab[];              // KEYSPACE words = 128KB
    uint32_t* tabS = tab;                          // KEYSPACE/2 words each
    uint32_t* tabD = tab + KEYSPACE/2;
    int b = blockIdx.x, t = threadIdx.x;

    for (int i = t; i < KEYSPACE; i += 256) tab[i] = 0;
    __syncthreads();

    int sk[4], dk[4];
#pragma unroll
    for (int m = 0; m < 4; ++m) {
        int i = b*LL + t + m*256;
        unsigned k1 = (unsigned)(sid[i]*8 + (ssn[i]-1));
        unsigned k2 = (unsigned)(did[i]*8 + (dsn[i]-1));
        k1 = min(k1, (unsigned)(KEYSPACE-1));
        k2 = min(k2, (unsigned)(KEYSPACE-1));
        sk[m] = (int)k1; dk[m] = (int)k2;
        atomicAdd(&tabS[k1>>1], 1u << ((k1&1)*16));
        atomicAdd(&tabD[k2>>1], 1u << ((k2&1)*16));
    }
    __syncthreads();

#pragma unroll
    for (int m = 0; m < 4; ++m) {
        int i = t + m*256;
        int k1 = sk[m], k2 = dk[m];
        float selfS  = (float)((tabS[k1>>1] >> ((k1&1)*16)) & 0xFFFFu);
        float crossS = (float)((tabD[k1>>1] >> ((k1&1)*16)) & 0xFFFFu);
        float selfD  = (float)((tabD[k2>>1] >> ((k2&1)*16)) & 0xFFFFu);
        float crossD = (float)((tabS[k2>>1] >> ((k2&1)*16)) & 0xFFFFu);
        float vs = (k1 >= 8) ? 1.f : 0.f;   // id != 0
        float vd = (k2 >= 8) ? 1.f : 0.f;
        g_cnt[       b*LL + i] = make_float2(selfS*vs,  crossS*vs);
        g_cnt[BL +   b*LL + i] = make_float2(selfD*vd,  crossD*vd);
    }
}

// ============================================================
// Fused agg-MLP + enc (piecewise-linear table) kernel.
// One warp per element-side; lane L covers d' = L, L+32, L+64, L+96.
// P/Q tables + all small weights staged in shared memory.
// ============================================================
__global__ __launch_bounds__(512, 1)
void k_mlp(const int* __restrict__ ssn, const int* __restrict__ dsn,
           const float* __restrict__ aw1, const float* __restrict__ ab1,
           const float* __restrict__ aw2, const float* __restrict__ ab2,
           const float* __restrict__ eb2, float* __restrict__ out) {
    extern __shared__ float sm[];
    float* sP   = sm;                 // NK*DD
    float* sQ   = sP + NK*DD;         // NK*DD
    float* sT   = sQ + NK*DD;         // DD
    float* sAW1 = sT + DD;            // SS*DD
    float* sAB1 = sAW1 + SS*DD;       // DD
    float* sW2a = sAB1 + DD;          // DD
    float* sW2b = sW2a + DD;          // DD
    float* sEB2 = sW2b + DD;          // DD
    float* sAB2 = sEB2 + DD;          // 2

    int tid = threadIdx.x;
    for (int i = tid; i < NK*DD; i += blockDim.x) { sP[i] = g_P[i]; sQ[i] = g_Q[i]; }
    for (int i = tid; i < DD; i += blockDim.x) {
        sT[i]   = g_sortedT[i];
        sAB1[i] = ab1[i];
        sW2a[i] = aw2[i*2 + 0];
        sW2b[i] = aw2[i*2 + 1];
        sEB2[i] = eb2[i];
    }
    for (int i = tid; i < SS*DD; i += blockDim.x) sAW1[i] = aw1[i];
    if (tid < 2) sAB2[tid] = ab2[tid];
    __syncthreads();

    int lane = tid & 31;
    int gw = blockIdx.x*(blockDim.x >> 5) + (tid >> 5);
    int W  = gridDim.x*(blockDim.x >> 5);
    float ab2_0 = sAB2[0], ab2_1 = sAB2[1];

    for (int e = gw; e < NELEM; e += W) {
        int side = e >> 16;           // BL == 65536
        int bl   = e & 65535;
        float2 v = g_cnt[e];
        int s = ((side ? dsn : ssn)[bl]) - 1;   // 0..7
        const float* w1r = sAW1 + s*DD;

        // agg: h_c = relu(v_c * w1[s] + b1); y = 0.5*(h0+h1)@w2 + b2
        float a0 = 0.f, a1 = 0.f;
#pragma unroll
        for (int m = 0; m < 4; ++m) {
            int d = lane + 32*m;
            float w = w1r[d], bb = sAB1[d];
            float h = fmaxf(fmaf(v.x, w, bb), 0.f) + fmaxf(fmaf(v.y, w, bb), 0.f);
            a0 = fmaf(h, sW2a[d], a0);
            a1 = fmaf(h, sW2b[d], a1);
        }
#pragma unroll
        for (int off = 16; off; off >>= 1) {
            a0 += __shfl_xor_sync(0xffffffffu, a0, off);
            a1 += __shfl_xor_sync(0xffffffffu, a1, off);
        }
        float y0 = fmaf(0.5f, a0, ab2_0);
        float y1 = fmaf(0.5f, a1, ab2_1);

        // interval index k = #{sortedT < y}  (uniform across warp -> bcast LDS)
        int k0 = 0, k1 = 0;
#pragma unroll
        for (int step = 128; step; step >>= 1) {
            int n0 = k0 + step; if (n0 <= 128 && sT[n0-1] < y0) k0 = n0;
            int n1 = k1 + step; if (n1 <= 128 && sT[n1-1] < y1) k1 = n1;
        }
        const float* P0 = sP + k0*DD; const float* Q0 = sQ + k0*DD;
        const float* P1 = sP + k1*DD; const float* Q1 = sQ + k1*DD;

        float* op = out + (size_t)e * DD;
#pragma unroll
        for (int m = 0; m < 4; ++m) {
            int d = lane + 32*m;
            float r = fmaf(y0, P0[d], Q0[d]) + fmaf(y1, P1[d], Q1[d]) + 2.f*sEB2[d];
            op[d] = r;
        }
    }
}

// ============================================================
extern "C" void kernel_launch(void* const* d_in, const int* in_sizes, int n_in,
                              void* d_out, int out_size) {
    const int*   sid = (const int*)d_in[0];
    const int*   did = (const int*)d_in[1];
    const int*   ssn = (const int*)d_in[2];
    const int*   dsn = (const int*)d_in[3];
    // d_in[4] = num_snapshots (compile-time SS=8)
    const float* aw1 = (const float*)d_in[5];
    const float* ab1 = (const float*)d_in[6];
    const float* aw2 = (const float*)d_in[7];
    const float* ab2 = (const float*)d_in[8];
    const float* ew1 = (const float*)d_in[9];
    const float* eb1 = (const float*)d_in[10];
    const float* ew2 = (const float*)d_in[11];
    const float* eb2 = (const float*)d_in[12];
    float* out = (float*)d_out;

    size_t cntSmem = (size_t)KEYSPACE * sizeof(uint32_t);                 // 128 KB
    size_t mlpSmem = (size_t)(2*NK*DD + DD + SS*DD + 4*DD + 2) * sizeof(float); // ~138.8 KB
    cudaFuncSetAttribute(k_count, cudaFuncAttributeMaxDynamicSharedMemorySize, (int)cntSmem);
    cudaFuncSetAttribute(k_mlp,   cudaFuncAttributeMaxDynamicSharedMemorySize, (int)mlpSmem);

    k_prep_sort<<<1, DD>>>(ew1, eb1);
    k_prep_table<<<NK, DD>>>(ew1, eb1, ew2);
    k_count<<<BB, 256, cntSmem>>>(sid, did, ssn, dsn);
    k_mlp<<<148, 512, mlpSmem>>>(ssn, dsn, aw1, ab1, aw2, ab2, eb2, out);
}

// round 3
// speedup vs baseline: 1.2915x; 1.2915x over previous
#include <cuda_runtime.h>
#include <cstdint>

#define BB 64
#define LL 1024
#define SS 8
#define DD 128
#define BL (BB*LL)          // 65536
#define NELEM (2*BL)        // 131072 element-sides
#define NK (DD+1)           // 129 relu-interval table rows
#define KEYSPACE 32768      // id*8 + (snap-1)
#define GT (SS*1025)        // g-table entries (s, count 0..1024)

// ---- device scratch ----
__device__ float    g_sortedT[DD];
__device__ int      g_rank[DD];
__device__ float    g_P[NK*DD];
__device__ float    g_Q[NK*DD];        // includes folded eb2
__device__ float2   g_g[GT];           // agg-MLP lookup: y contribution per (s, count)
__device__ uint32_t g_cnt[NELEM];      // packed: cx | cy<<11 | s<<22

// ============================================================
// Prologue 1: sort enc relu breakpoints t_d = -b1[d]/w1[d]
// ============================================================
__global__ void k_prep_sort(const float* __restrict__ ew1,
                            const float* __restrict__ eb1) {
    __shared__ float t[DD];
    int d = threadIdx.x;
    float w = ew1[d], b = eb1[d];
    float td = (w != 0.0f) ? (-b / w) : __int_as_float(0x7f800000);
    t[d] = td;
    __syncthreads();
    int r = 0;
    for (int j = 0; j < DD; ++j) {
        float tj = t[j];
        r += (tj < td || (tj == td && j < d)) ? 1 : 0;
    }
    g_rank[d] = r;
    g_sortedT[r] = td;
}

// ============================================================
// Prologue 2: per-interval prefix tables (eb2 folded into Q)
// ============================================================
__global__ void k_prep_table(const float* __restrict__ ew1,
                             const float* __restrict__ eb1,
                             const float* __restrict__ ew2,
                             const float* __restrict__ eb2) {
    __shared__ float sw[DD], sb[DD];
    __shared__ int   sr[DD];
    int k = blockIdx.x, dp = threadIdx.x;
    sw[dp] = ew1[dp];
    sb[dp] = eb1[dp];
    sr[dp] = g_rank[dp];
    __syncthreads();
    float p = 0.f, q = eb2[dp];   // fold one eb2 into each of the two Q terms
    for (int d = 0; d < DD; ++d) {
        float w = sw[d], b = sb[d];
        int   r = sr[d];
        bool act = (w > 0.f) ? (r < k) : ((w < 0.f) ? (r >= k) : (b > 0.f));
        if (act) {
            float w2 = ew2[d*DD + dp];
            p = fmaf(w, w2, p);
            q = fmaf(b, w2, q);
        }
    }
    g_P[k*DD + dp] = p;
    g_Q[k*DD + dp] = q;
}

// ============================================================
// Prologue 3: agg-MLP lookup table over integer counts.
//   g[s][c][ch] = sum_d relu(c*aw1[s,d]+ab1[d]) * aw2[d,ch]
// one warp per (s,c)
// ============================================================
__global__ void k_prep_gtab(const float* __restrict__ aw1,
                            const float* __restrict__ ab1,
                            const float* __restrict__ aw2) {
    int gw = blockIdx.x*8 + (threadIdx.x >> 5);
    int lane = threadIdx.x & 31;
    if (gw >= GT) return;
    int s = gw & 7;
    int c = gw >> 3;
    float fc = (float)c;
    float a0 = 0.f, a1 = 0.f;
#pragma unroll
    for (int m = 0; m < 4; ++m) {
        int d = lane + 32*m;
        float h = fmaxf(fmaf(fc, aw1[s*DD + d], ab1[d]), 0.f);
        a0 = fmaf(h, aw2[2*d + 0], a0);
        a1 = fmaf(h, aw2[2*d + 1], a1);
    }
#pragma unroll
    for (int off = 16; off; off >>= 1) {
        a0 += __shfl_xor_sync(0xffffffffu, a0, off);
        a1 += __shfl_xor_sync(0xffffffffu, a1, off);
    }
    if (lane == 0) g_g[s*1025 + c] = make_float2(a0, a1);
}

// ============================================================
// Count kernel: per-batch smem histogram of packed (id,snap) keys.
// Emits packed (cx, cy, s) per element-side.
// ============================================================
__global__ void k_count(const int* __restrict__ sid, const int* __restrict__ did,
                        const int* __restrict__ ssn, const int* __restrict__ dsn) {
    extern __shared__ uint32_t tab[];              // 128 KB
    uint32_t* tabS = tab;
    uint32_t* tabD = tab + KEYSPACE/2;
    int b = blockIdx.x, t = threadIdx.x;

    for (int i = t; i < KEYSPACE; i += 256) tab[i] = 0;
    __syncthreads();

    int sk[4], dk[4];
#pragma unroll
    for (int m = 0; m < 4; ++m) {
        int i = b*LL + t + m*256;
        unsigned k1 = (unsigned)(sid[i]*8 + (ssn[i]-1));
        unsigned k2 = (unsigned)(did[i]*8 + (dsn[i]-1));
        k1 = min(k1, (unsigned)(KEYSPACE-1));
        k2 = min(k2, (unsigned)(KEYSPACE-1));
        sk[m] = (int)k1; dk[m] = (int)k2;
        atomicAdd(&tabS[k1>>1], 1u << ((k1&1)*16));
        atomicAdd(&tabD[k2>>1], 1u << ((k2&1)*16));
    }
    __syncthreads();

#pragma unroll
    for (int m = 0; m < 4; ++m) {
        int i = t + m*256;
        int k1 = sk[m], k2 = dk[m];
        uint32_t cxS = (tabS[k1>>1] >> ((k1&1)*16)) & 0xFFFFu;
        uint32_t cyS = (tabD[k1>>1] >> ((k1&1)*16)) & 0xFFFFu;
        uint32_t cxD = (tabD[k2>>1] >> ((k2&1)*16)) & 0xFFFFu;
        uint32_t cyD = (tabS[k2>>1] >> ((k2&1)*16)) & 0xFFFFu;
        if (k1 < 8) { cxS = 0; cyS = 0; }   // id == 0 -> invalid -> counts zeroed
        if (k2 < 8) { cxD = 0; cyD = 0; }
        g_cnt[     b*LL + i] = cxS | (cyS << 11) | ((uint32_t)(k1 & 7) << 22);
        g_cnt[BL + b*LL + i] = cxD | (cyD << 11) | ((uint32_t)(k2 & 7) << 22);
    }
}

// ============================================================
// Main kernel: per element-side, table-lookup y, ballot interval
// search, vectorized P/Q epilogue + float4 store.
// ============================================================
struct ElemCtx {
    const float2* sG;
    const float*  sP;
    const float*  sQ;
    float ab2_0, ab2_1;
    float t0, t1, t2, t3;
    int lane;
};

__device__ __forceinline__ void process_elem(int e, const ElemCtx& C,
                                             float* __restrict__ out) {
    uint32_t pk = g_cnt[e];
    int cx = pk & 0x7FF;
    int cy = (pk >> 11) & 0x7FF;
    int s  = pk >> 22;
    float2 gx = C.sG[s*1025 + cx];
    float2 gy = C.sG[s*1025 + cy];
    float y0 = fmaf(0.5f, gx.x + gy.x, C.ab2_0);
    float y1 = fmaf(0.5f, gx.y + gy.y, C.ab2_1);

    int k0 = __popc(__ballot_sync(0xffffffffu, C.t0 < y0))
           + __popc(__ballot_sync(0xffffffffu, C.t1 < y0))
           + __popc(__ballot_sync(0xffffffffu, C.t2 < y0))
           + __popc(__ballot_sync(0xffffffffu, C.t3 < y0));
    int k1 = __popc(__ballot_sync(0xffffffffu, C.t0 < y1))
           + __popc(__ballot_sync(0xffffffffu, C.t1 < y1))
           + __popc(__ballot_sync(0xffffffffu, C.t2 < y1))
           + __popc(__ballot_sync(0xffffffffu, C.t3 < y1));

    int o = C.lane * 4;
    float4 p0 = *(const float4*)&C.sP[k0*DD + o];
    float4 q0 = *(const float4*)&C.sQ[k0*DD + o];
    float4 p1 = *(const float4*)&C.sP[k1*DD + o];
    float4 q1 = *(const float4*)&C.sQ[k1*DD + o];
    float4 r;
    r.x = fmaf(y0, p0.x, q0.x) + fmaf(y1, p1.x, q1.x);
    r.y = fmaf(y0, p0.y, q0.y) + fmaf(y1, p1.y, q1.y);
    r.z = fmaf(y0, p0.z, q0.z) + fmaf(y1, p1.z, q1.z);
    r.w = fmaf(y0, p0.w, q0.w) + fmaf(y1, p1.w, q1.w);
    *(float4*)&out[(size_t)e * DD + o] = r;
}

__global__ __launch_bounds__(512, 1)
void k_mlp(const float* __restrict__ ab2, float* __restrict__ out) {
    extern __shared__ float sm[];
    float*  sP = sm;                       // NK*DD
    float*  sQ = sm + NK*DD;               // NK*DD
    float2* sG = (float2*)(sm + 2*NK*DD);  // GT float2

    int tid = threadIdx.x;
    for (int i = tid; i < NK*DD; i += 512) { sP[i] = g_P[i]; sQ[i] = g_Q[i]; }
    for (int i = tid; i < GT; i += 512) sG[i] = g_g[i];

    ElemCtx C;
    C.sG = sG; C.sP = sP; C.sQ = sQ;
    C.ab2_0 = __ldg(&ab2[0]); C.ab2_1 = __ldg(&ab2[1]);
    C.lane = tid & 31;
    C.t0 = g_sortedT[C.lane];
    C.t1 = g_sortedT[C.lane + 32];
    C.t2 = g_sortedT[C.lane + 64];
    C.t3 = g_sortedT[C.lane + 96];
    __syncthreads();

    int gw = blockIdx.x * 16 + (tid >> 5);
    const int W = 148 * 16;
    for (int e = gw; e < NELEM; e += 2*W) {
        process_elem(e, C, out);
        int e2 = e + W;
        if (e2 < NELEM) process_elem(e2, C, out);
    }
}

// ============================================================
extern "C" void kernel_launch(void* const* d_in, const int* in_sizes, int n_in,
                              void* d_out, int out_size) {
    const int*   sid = (const int*)d_in[0];
    const int*   did = (const int*)d_in[1];
    const int*   ssn = (const int*)d_in[2];
    const int*   dsn = (const int*)d_in[3];
    const float* aw1 = (const float*)d_in[5];
    const float* ab1 = (const float*)d_in[6];
    const float* aw2 = (const float*)d_in[7];
    const float* ab2 = (const float*)d_in[8];
    const float* ew1 = (const float*)d_in[9];
    const float* eb1 = (const float*)d_in[10];
    const float* ew2 = (const float*)d_in[11];
    const float* eb2 = (const float*)d_in[12];
    float* out = (float*)d_out;

    size_t cntSmem = (size_t)KEYSPACE * sizeof(uint32_t);                    // 128 KB
    size_t mlpSmem = (size_t)(2*NK*DD)*sizeof(float) + (size_t)GT*sizeof(float2); // ~193 KB
    cudaFuncSetAttribute(k_count, cudaFuncAttributeMaxDynamicSharedMemorySize, (int)cntSmem);
    cudaFuncSetAttribute(k_mlp,   cudaFuncAttributeMaxDynamicSharedMemorySize, (int)mlpSmem);

    k_prep_sort<<<1, DD>>>(ew1, eb1);
    k_prep_table<<<NK, DD>>>(ew1, eb1, ew2, eb2);
    k_prep_gtab<<<(GT + 7)/8, 256>>>(aw1, ab1, aw2);
    k_count<<<BB, 256, cntSmem>>>(sid, did, ssn, dsn);
    k_mlp<<<148, 512, mlpSmem>>>(ab2, out);
}

// round 5
// speedup vs baseline: 2.0788x; 1.6096x over previous
#include <cuda_runtime.h>
#include <cstdint>

#define BB 64
#define LL 1024
#define SS 8
#define DD 128
#define BL (BB*LL)          // 65536
#define NELEM (2*BL)        // 131072 element-sides
#define NK (DD+1)           // 129 relu-interval table rows
#define KEYSPACE 32768      // id*8 + (snap-1)
#define GT (SS*1025)        // g-table entries (s, count 0..1024)

// ---- device scratch ----
__device__ float    g_sortedT[DD];
__device__ float    g_P[NK*DD];
__device__ float    g_Q[NK*DD];        // includes folded eb2
__device__ float2   g_g[GT];           // agg-MLP lookup per (s, count)
__device__ uint32_t g_cnt[NELEM];      // packed: cx | cy<<11 | s<<22

// ============================================================
// Fused prologue + count kernel. Block roles by blockIdx.x:
//   [0,64)    : per-batch histogram count        (needs 128KB smem)
//   [64,81)   : P/Q interval tables, 8 k per blk (stages ew2, local sort)
//   [81,90)   : agg-MLP g-table, thread per (s,c)
// ============================================================
__global__ __launch_bounds__(1024, 1)
void k_fused(const int* __restrict__ sid, const int* __restrict__ did,
             const int* __restrict__ ssn, const int* __restrict__ dsn,
             const float* __restrict__ aw1, const float* __restrict__ ab1,
             const float* __restrict__ aw2,
             const float* __restrict__ ew1, const float* __restrict__ eb1,
             const float* __restrict__ ew2, const float* __restrict__ eb2) {
    extern __shared__ uint32_t smraw[];
    int bid = blockIdx.x;
    int tid = threadIdx.x;

    if (bid < 64) {
        // ---------------- count section ----------------
        uint32_t* tabS = smraw;                 // KEYSPACE/2 words
        uint32_t* tabD = smraw + KEYSPACE/2;
        int b = bid;
        for (int i = tid; i < KEYSPACE; i += 1024) smraw[i] = 0;
        __syncthreads();

        int i = b*LL + tid;
        unsigned k1 = (unsigned)(sid[i]*8 + (ssn[i]-1));
        unsigned k2 = (unsigned)(did[i]*8 + (dsn[i]-1));
        k1 = min(k1, (unsigned)(KEYSPACE-1));
        k2 = min(k2, (unsigned)(KEYSPACE-1));
        atomicAdd(&tabS[k1>>1], 1u << ((k1&1)*16));
        atomicAdd(&tabD[k2>>1], 1u << ((k2&1)*16));
        __syncthreads();

        uint32_t cxS = (tabS[k1>>1] >> ((k1&1)*16)) & 0xFFFFu;
        uint32_t cyS = (tabD[k1>>1] >> ((k1&1)*16)) & 0xFFFFu;
        uint32_t cxD = (tabD[k2>>1] >> ((k2&1)*16)) & 0xFFFFu;
        uint32_t cyD = (tabS[k2>>1] >> ((k2&1)*16)) & 0xFFFFu;
        if (k1 < 8) { cxS = 0; cyS = 0; }     // id == 0 -> invalid
        if (k2 < 8) { cxD = 0; cyD = 0; }
        g_cnt[     b*LL + tid] = cxS | (cyS << 11) | ((k1 & 7u) << 22);
        g_cnt[BL + b*LL + tid] = cxD | (cyD << 11) | ((k2 & 7u) << 22);

    } else if (bid < 81) {
        // ---------------- P/Q table section ----------------
        float* sm   = (float*)smraw;
        float* sEW2 = sm;            // 16384
        float* sW   = sm + 16384;    // 128
        float* sB   = sm + 16512;    // 128
        float* sT   = sm + 16640;    // 128
        int*   sR   = (int*)(sm + 16768); // 128
        int bid2 = bid - 64;

        for (int i = tid; i < DD*DD; i += 1024) sEW2[i] = ew2[i];
        if (tid < DD) {
            float w = ew1[tid], b = eb1[tid];
            sW[tid] = w; sB[tid] = b;
            sT[tid] = (w != 0.0f) ? (-b / w) : __int_as_float(0x7f800000);
        }
        __syncthreads();
        if (tid < DD) {
            float td = sT[tid];
            int r = 0;
            for (int j = 0; j < DD; ++j) {
                float tj = sT[j];
                r += (tj < td || (tj == td && j < tid)) ? 1 : 0;
            }
            sR[tid] = r;
            if (bid2 == 0) g_sortedT[r] = td;
        }
        __syncthreads();

        int j  = tid >> 7;          // 0..7
        int dp = tid & 127;
        int k  = bid2*8 + j;
        if (k <= DD) {
            float p = 0.f, q = eb2[dp];
#pragma unroll 8
            for (int d = 0; d < DD; ++d) {
                float w = sW[d], b = sB[d];
                int   r = sR[d];
                bool act = (w > 0.f) ? (r < k) : ((w < 0.f) ? (r >= k) : (b > 0.f));
                if (act) {
                    float w2 = sEW2[d*DD + dp];
                    p = fmaf(w, w2, p);
                    q = fmaf(b, w2, q);
                }
            }
            g_P[k*DD + dp] = p;
            g_Q[k*DD + dp] = q;
        }

    } else {
        // ---------------- g-table section ----------------
        float* sm   = (float*)smraw;
        float* sAW1 = sm;            // 1024
        float* sAB1 = sm + 1024;     // 128
        float* sW2a = sm + 1152;     // 128
        float* sW2b = sm + 1280;     // 128
        sAW1[tid] = aw1[tid];        // SS*DD == 1024 == blockDim
        if (tid < DD) {
            sAB1[tid] = ab1[tid];
            sW2a[tid] = aw2[2*tid + 0];
            sW2b[tid] = aw2[2*tid + 1];
        }
        __syncthreads();

        int idx = (bid - 81)*1024 + tid;
        if (idx < GT) {
            int s = idx / 1025;
            int c = idx - s*1025;
            float fc = (float)c;
            const float* w1r = sAW1 + s*DD;
            float a0 = 0.f, a1 = 0.f;
#pragma unroll 8
            for (int d = 0; d < DD; ++d) {
                float h = fmaxf(fmaf(fc, w1r[d], sAB1[d]), 0.f);
                a0 = fmaf(h, sW2a[d], a0);
                a1 = fmaf(h, sW2b[d], a1);
            }
            g_g[idx] = make_float2(a0, a1);
        }
    }
}

// ============================================================
// Main kernel: per element-side, table-lookup y, ballot interval
// search, vectorized P/Q epilogue + float4 store.
// ============================================================
struct ElemCtx {
    const float2* sG;
    const float*  sP;
    const float*  sQ;
    float ab2_0, ab2_1;
    float t0, t1, t2, t3;
    int lane;
};

__device__ __forceinline__ void process_elem(int e, uint32_t pk, const ElemCtx& C,
                                             float* __restrict__ out) {
    int cx = pk & 0x7FF;
    int cy = (pk >> 11) & 0x7FF;
    int s  = pk >> 22;
    float2 gx = C.sG[s*1025 + cx];
    float2 gy = C.sG[s*1025 + cy];
    float y0 = fmaf(0.5f, gx.x + gy.x, C.ab2_0);
    float y1 = fmaf(0.5f, gx.y + gy.y, C.ab2_1);

    int k0 = __popc(__ballot_sync(0xffffffffu, C.t0 < y0))
           + __popc(__ballot_sync(0xffffffffu, C.t1 < y0))
           + __popc(__ballot_sync(0xffffffffu, C.t2 < y0))
           + __popc(__ballot_sync(0xffffffffu, C.t3 < y0));
    int k1 = __popc(__ballot_sync(0xffffffffu, C.t0 < y1))
           + __popc(__ballot_sync(0xffffffffu, C.t1 < y1))
           + __popc(__ballot_sync(0xffffffffu, C.t2 < y1))
           + __popc(__ballot_sync(0xffffffffu, C.t3 < y1));

    int o = C.lane * 4;
    float4 p0 = *(const float4*)&C.sP[k0*DD + o];
    float4 q0 = *(const float4*)&C.sQ[k0*DD + o];
    float4 p1 = *(const float4*)&C.sP[k1*DD + o];
    float4 q1 = *(const float4*)&C.sQ[k1*DD + o];
    float4 r;
    r.x = fmaf(y0, p0.x, q0.x) + fmaf(y1, p1.x, q1.x);
    r.y = fmaf(y0, p0.y, q0.y) + fmaf(y1, p1.y, q1.y);
    r.z = fmaf(y0, p0.z, q0.z) + fmaf(y1, p1.z, q1.z);
    r.w = fmaf(y0, p0.w, q0.w) + fmaf(y1, p1.w, q1.w);
    *(float4*)&out[(size_t)e * DD + o] = r;
}

__global__ __launch_bounds__(1024, 1)
void k_mlp(const float* __restrict__ ab2, float* __restrict__ out) {
    extern __shared__ float sm[];
    float*  sP = sm;                       // NK*DD
    float*  sQ = sm + NK*DD;               // NK*DD
    float2* sG = (float2*)(sm + 2*NK*DD);  // GT float2

    int tid = threadIdx.x;
    for (int i = tid; i < NK*DD; i += 1024) { sP[i] = g_P[i]; sQ[i] = g_Q[i]; }
    for (int i = tid; i < GT; i += 1024) sG[i] = g_g[i];

    ElemCtx C;
    C.sG = sG; C.sP = sP; C.sQ = sQ;
    C.ab2_0 = __ldg(&ab2[0]); C.ab2_1 = __ldg(&ab2[1]);
    C.lane = tid & 31;
    C.t0 = g_sortedT[C.lane];
    C.t1 = g_sortedT[C.lane + 32];
    C.t2 = g_sortedT[C.lane + 64];
    C.t3 = g_sortedT[C.lane + 96];
    __syncthreads();

    const int W = 148 * 32;
    int e = blockIdx.x * 32 + (tid >> 5);
    uint32_t pk = (e < NELEM) ? g_cnt[e] : 0;
    while (e < NELEM) {
        int en = e + W;
        uint32_t pkn = (en < NELEM) ? g_cnt[en] : 0;   // prefetch next
        process_elem(e, pk, C, out);
        e = en; pk = pkn;
    }
}

// ============================================================
extern "C" void kernel_launch(void* const* d_in, const int* in_sizes, int n_in,
                              void* d_out, int out_size) {
    const int*   sid = (const int*)d_in[0];
    const int*   did = (const int*)d_in[1];
    const int*   ssn = (const int*)d_in[2];
    const int*   dsn = (const int*)d_in[3];
    const float* aw1 = (const float*)d_in[5];
    const float* ab1 = (const float*)d_in[6];
    const float* aw2 = (const float*)d_in[7];
    const float* ab2 = (const float*)d_in[8];
    const float* ew1 = (const float*)d_in[9];
    const float* eb1 = (const float*)d_in[10];
    const float* ew2 = (const float*)d_in[11];
    const float* eb2 = (const float*)d_in[12];
    float* out = (float*)d_out;

    size_t fusedSmem = (size_t)KEYSPACE * sizeof(uint32_t);                  // 128 KB
    size_t mlpSmem = (size_t)(2*NK*DD)*sizeof(float) + (size_t)GT*sizeof(float2); // ~193 KB
    cudaFuncSetAttribute(k_fused, cudaFuncAttributeMaxDynamicSharedMemorySize, (int)fusedSmem);
    cudaFuncSetAttribute(k_mlp,   cudaFuncAttributeMaxDynamicSharedMemorySize, (int)mlpSmem);

    k_fused<<<90, 1024, fusedSmem>>>(sid, did, ssn, dsn,
                                     aw1, ab1, aw2, ew1, eb1, ew2, eb2);
    k_mlp<<<148, 1024, mlpSmem>>>(ab2, out);
}

// round 6
// speedup vs baseline: 2.4700x; 1.1882x over previous
#include <cuda_runtime.h>
#include <cstdint>

#define BB 64
#define LL 1024
#define SS 8
#define DD 128
#define BL (BB*LL)          // 65536
#define NELEM (2*BL)        // 131072 element-sides
#define NK (DD+1)           // 129 relu-interval table rows
#define KEYSPACE 32768      // id*8 + (snap-1)
#define GT (SS*1025)        // g-table entries (s, count 0..1024)
#define CMAX 32             // joint-table count range
#define NTAB (SS*CMAX*CMAX) // 8192 joint-table rows

// ---- device scratch ----
__device__ float    g_sortedT[DD];
__device__ float    g_P[NK*DD];
__device__ float    g_Q[NK*DD];        // includes folded eb2
__device__ float2   g_g[GT];           // agg-MLP lookup per (s, count)
__device__ uint32_t g_cnt[NELEM];      // packed: cx | cy<<11 | s<<22
__device__ float4   g_tab[NTAB*32];    // joint output table, 4MB

// ============================================================
// Fused prologue + count kernel. Block roles by blockIdx.x:
//   [0,64)    : per-batch histogram count        (128KB smem)
//   [64,81)   : P/Q interval tables, 8 k per blk
//   [81,90)   : agg-MLP g-table, thread per (s,c)
// ============================================================
__global__ __launch_bounds__(1024, 1)
void k_fused(const int* __restrict__ sid, const int* __restrict__ did,
             const int* __restrict__ ssn, const int* __restrict__ dsn,
             const float* __restrict__ aw1, const float* __restrict__ ab1,
             const float* __restrict__ aw2,
             const float* __restrict__ ew1, const float* __restrict__ eb1,
             const float* __restrict__ ew2, const float* __restrict__ eb2) {
    extern __shared__ uint32_t smraw[];
    int bid = blockIdx.x;
    int tid = threadIdx.x;

    if (bid < 64) {
        uint32_t* tabS = smraw;
        uint32_t* tabD = smraw + KEYSPACE/2;
        int b = bid;
        for (int i = tid; i < KEYSPACE; i += 1024) smraw[i] = 0;
        __syncthreads();

        int i = b*LL + tid;
        unsigned k1 = (unsigned)(sid[i]*8 + (ssn[i]-1));
        unsigned k2 = (unsigned)(did[i]*8 + (dsn[i]-1));
        k1 = min(k1, (unsigned)(KEYSPACE-1));
        k2 = min(k2, (unsigned)(KEYSPACE-1));
        atomicAdd(&tabS[k1>>1], 1u << ((k1&1)*16));
        atomicAdd(&tabD[k2>>1], 1u << ((k2&1)*16));
        __syncthreads();

        uint32_t cxS = (tabS[k1>>1] >> ((k1&1)*16)) & 0xFFFFu;
        uint32_t cyS = (tabD[k1>>1] >> ((k1&1)*16)) & 0xFFFFu;
        uint32_t cxD = (tabD[k2>>1] >> ((k2&1)*16)) & 0xFFFFu;
        uint32_t cyD = (tabS[k2>>1] >> ((k2&1)*16)) & 0xFFFFu;
        if (k1 < 8) { cxS = 0; cyS = 0; }     // id == 0 -> invalid
        if (k2 < 8) { cxD = 0; cyD = 0; }
        g_cnt[     b*LL + tid] = cxS | (cyS << 11) | ((k1 & 7u) << 22);
        g_cnt[BL + b*LL + tid] = cxD | (cyD << 11) | ((k2 & 7u) << 22);

    } else if (bid < 81) {
        float* sm   = (float*)smraw;
        float* sEW2 = sm;
        float* sW   = sm + 16384;
        float* sB   = sm + 16512;
        float* sT   = sm + 16640;
        int*   sR   = (int*)(sm + 16768);
        int bid2 = bid - 64;

        for (int i = tid; i < DD*DD; i += 1024) sEW2[i] = ew2[i];
        if (tid < DD) {
            float w = ew1[tid], b = eb1[tid];
            sW[tid] = w; sB[tid] = b;
            sT[tid] = (w != 0.0f) ? (-b / w) : __int_as_float(0x7f800000);
        }
        __syncthreads();
        if (tid < DD) {
            float td = sT[tid];
            int r = 0;
            for (int j = 0; j < DD; ++j) {
                float tj = sT[j];
                r += (tj < td || (tj == td && j < tid)) ? 1 : 0;
            }
            sR[tid] = r;
            if (bid2 == 0) g_sortedT[r] = td;
        }
        __syncthreads();

        int j  = tid >> 7;
        int dp = tid & 127;
        int k  = bid2*8 + j;
        if (k <= DD) {
            float p = 0.f, q = eb2[dp];
#pragma unroll 8
            for (int d = 0; d < DD; ++d) {
                float w = sW[d], b = sB[d];
                int   r = sR[d];
                bool act = (w > 0.f) ? (r < k) : ((w < 0.f) ? (r >= k) : (b > 0.f));
                if (act) {
                    float w2 = sEW2[d*DD + dp];
                    p = fmaf(w, w2, p);
                    q = fmaf(b, w2, q);
                }
            }
            g_P[k*DD + dp] = p;
            g_Q[k*DD + dp] = q;
        }

    } else {
        float* sm   = (float*)smraw;
        float* sAW1 = sm;            // 1024
        float* sAB1 = sm + 1024;     // 128
        float* sW2a = sm + 1152;     // 128
        float* sW2b = sm + 1280;     // 128
        sAW1[tid] = aw1[tid];        // SS*DD == 1024 == blockDim
        if (tid < DD) {
            sAB1[tid] = ab1[tid];
            sW2a[tid] = aw2[2*tid + 0];
            sW2b[tid] = aw2[2*tid + 1];
        }
        __syncthreads();

        int idx = (bid - 81)*1024 + tid;
        if (idx < GT) {
            int s = idx / 1025;
            int c = idx - s*1025;
            float fc = (float)c;
            const float* w1r = sAW1 + s*DD;
            float a0 = 0.f, a1 = 0.f;
#pragma unroll 8
            for (int d = 0; d < DD; ++d) {
                float h = fmaxf(fmaf(fc, w1r[d], sAB1[d]), 0.f);
                a0 = fmaf(h, sW2a[d], a0);
                a1 = fmaf(h, sW2b[d], a1);
            }
            g_g[idx] = make_float2(a0, a1);
        }
    }
}

// ============================================================
// Shared element math: (s,cx,cy) -> 128-float row (lane covers 4).
// ============================================================
__device__ __forceinline__ float4 elem_row(int s, int cx, int cy,
                                           float ab2_0, float ab2_1, int lane) {
    float2 gx = g_g[s*1025 + cx];
    float2 gy = g_g[s*1025 + cy];
    float y0 = fmaf(0.5f, gx.x + gy.x, ab2_0);
    float y1 = fmaf(0.5f, gx.y + gy.y, ab2_1);

    float t0 = g_sortedT[lane];
    float t1 = g_sortedT[lane + 32];
    float t2 = g_sortedT[lane + 64];
    float t3 = g_sortedT[lane + 96];
    int k0 = __popc(__ballot_sync(0xffffffffu, t0 < y0))
           + __popc(__ballot_sync(0xffffffffu, t1 < y0))
           + __popc(__ballot_sync(0xffffffffu, t2 < y0))
           + __popc(__ballot_sync(0xffffffffu, t3 < y0));
    int k1 = __popc(__ballot_sync(0xffffffffu, t0 < y1))
           + __popc(__ballot_sync(0xffffffffu, t1 < y1))
           + __popc(__ballot_sync(0xffffffffu, t2 < y1))
           + __popc(__ballot_sync(0xffffffffu, t3 < y1));

    const float4* P = (const float4*)g_P;
    const float4* Q = (const float4*)g_Q;
    float4 p0 = P[k0*32 + lane], q0 = Q[k0*32 + lane];
    float4 p1 = P[k1*32 + lane], q1 = Q[k1*32 + lane];
    float4 r;
    r.x = fmaf(y0, p0.x, q0.x) + fmaf(y1, p1.x, q1.x);
    r.y = fmaf(y0, p0.y, q0.y) + fmaf(y1, p1.y, q1.y);
    r.z = fmaf(y0, p0.z, q0.z) + fmaf(y1, p1.z, q1.z);
    r.w = fmaf(y0, p0.w, q0.w) + fmaf(y1, p1.w, q1.w);
    return r;
}

// ============================================================
// Joint-table generator: one warp per (s, cx, cy), cx,cy < 32.
// ============================================================
__global__ __launch_bounds__(1024, 1)
void k_tab(const float* __restrict__ ab2) {
    int w = blockIdx.x*32 + (threadIdx.x >> 5);   // 0..8191
    int lane = threadIdx.x & 31;
    float ab2_0 = __ldg(&ab2[0]), ab2_1 = __ldg(&ab2[1]);
    int s  = w >> 10;
    int cx = (w >> 5) & 31;
    int cy = w & 31;
    g_tab[w*32 + lane] = elem_row(s, cx, cy, ab2_0, ab2_1, lane);
}

// ============================================================
// Main kernel: pure gather-copy. Hot (cx,cy<4) rows cached in smem.
// ============================================================
__global__ __launch_bounds__(1024, 2)
void k_main(const float* __restrict__ ab2, float4* __restrict__ out) {
    extern __shared__ float4 sC[];      // 128 rows * 32 float4 = 64KB
    int tid = threadIdx.x;
    int lane = tid & 31;

    // stage hot sub-table: compact index (s<<4)|(cx<<2)|cy
    for (int i = tid; i < 128*32; i += 1024) {
        int ce = i >> 5;                 // compact entry
        int l4 = i & 31;
        int s  = ce >> 4;
        int cx = (ce >> 2) & 3;
        int cy = ce & 3;
        sC[i] = g_tab[(((s << 5) | cx)*32 + cy)*32 + l4];
    }
    __syncthreads();

    const int W = 296*32;
    int e = blockIdx.x*32 + (tid >> 5);
    uint32_t pk = (e < NELEM) ? g_cnt[e] : 0;
    while (e < NELEM) {
        int en = e + W;
        uint32_t pkn = (en < NELEM) ? g_cnt[en] : 0;

        int cx = pk & 0x7FF;
        int cy = (pk >> 11) & 0x7FF;
        int s  = pk >> 22;
        float4 r;
        if ((cx | cy) < 4) {
            r = sC[(((s << 2) | cx)*4 + cy)*32 + lane];
        } else if ((cx | cy) < CMAX) {
            r = g_tab[(((s << 5) | cx)*32 + cy)*32 + lane];
        } else {
            cx = min(cx, 1024); cy = min(cy, 1024);
            r = elem_row(s, cx, cy, __ldg(&ab2[0]), __ldg(&ab2[1]), lane);
        }
        out[e*32 + lane] = r;

        e = en; pk = pkn;
    }
}

// ============================================================
extern "C" void kernel_launch(void* const* d_in, const int* in_sizes, int n_in,
                              void* d_out, int out_size) {
    const int*   sid = (const int*)d_in[0];
    const int*   did = (const int*)d_in[1];
    const int*   ssn = (const int*)d_in[2];
    const int*   dsn = (const int*)d_in[3];
    const float* aw1 = (const float*)d_in[5];
    const float* ab1 = (const float*)d_in[6];
    const float* aw2 = (const float*)d_in[7];
    const float* ab2 = (const float*)d_in[8];
    const float* ew1 = (const float*)d_in[9];
    const float* eb1 = (const float*)d_in[10];
    const float* ew2 = (const float*)d_in[11];
    const float* eb2 = (const float*)d_in[12];
    float4* out = (float4*)d_out;

    size_t fusedSmem = (size_t)KEYSPACE * sizeof(uint32_t);   // 128 KB
    size_t mainSmem  = 128*32*sizeof(float4);                 // 64 KB
    cudaFuncSetAttribute(k_fused, cudaFuncAttributeMaxDynamicSharedMemorySize, (int)fusedSmem);
    cudaFuncSetAttribute(k_main,  cudaFuncAttributeMaxDynamicSharedMemorySize, (int)mainSmem);

    k_fused<<<90, 1024, fusedSmem>>>(sid, did, ssn, dsn,
                                     aw1, ab1, aw2, ew1, eb1, ew2, eb2);
    k_tab<<<256, 1024>>>(ab2);
    k_main<<<296, 1024, mainSmem>>>(ab2, out);
}

// round 7
// speedup vs baseline: 2.4903x; 1.0082x over previous
#include <cuda_runtime.h>
#include <cstdint>

#define BB 64
#define LL 1024
#define SS 8
#define DD 128
#define BL (BB*LL)          // 65536
#define NELEM (2*BL)        // 131072 element-sides
#define NK (DD+1)           // 129 relu-interval table rows
#define KEYSPACE 32768      // id*8 + (snap-1)
#define GT (SS*1025)        // g-table entries (s, count 0..1024)

// ---- device scratch ----
__device__ float    g_sortedT[DD];
__device__ float    g_P[NK*DD];
__device__ float    g_Q[NK*DD];        // includes folded eb2
__device__ float2   g_g[GT];           // agg-MLP lookup per (s, count)
__device__ uint32_t g_cnt[NELEM];      // packed: cx | cy<<11 | s<<22

// ============================================================
// Fused prologue + count kernel. Block roles by blockIdx.x:
//   [0,64)    : per-batch histogram count        (128KB smem)
//   [64,81)   : P/Q interval tables, 8 k per blk
//   [81,90)   : agg-MLP g-table, thread per (s,c)
// ============================================================
__global__ __launch_bounds__(1024, 1)
void k_fused(const int* __restrict__ sid, const int* __restrict__ did,
             const int* __restrict__ ssn, const int* __restrict__ dsn,
             const float* __restrict__ aw1, const float* __restrict__ ab1,
             const float* __restrict__ aw2,
             const float* __restrict__ ew1, const float* __restrict__ eb1,
             const float* __restrict__ ew2, const float* __restrict__ eb2) {
    extern __shared__ uint32_t smraw[];
    int bid = blockIdx.x;
    int tid = threadIdx.x;

    if (bid < 64) {
        // ---------------- count section ----------------
        uint32_t* tabS = smraw;
        uint32_t* tabD = smraw + KEYSPACE/2;
        int b = bid;
        uint4* z = (uint4*)smraw;
#pragma unroll
        for (int i = 0; i < 8; ++i) z[tid + i*1024] = make_uint4(0,0,0,0);
        __syncthreads();

        int i = b*LL + tid;
        unsigned k1 = (unsigned)(sid[i]*8 + (ssn[i]-1));
        unsigned k2 = (unsigned)(did[i]*8 + (dsn[i]-1));
        k1 = min(k1, (unsigned)(KEYSPACE-1));
        k2 = min(k2, (unsigned)(KEYSPACE-1));
        atomicAdd(&tabS[k1>>1], 1u << ((k1&1)*16));
        atomicAdd(&tabD[k2>>1], 1u << ((k2&1)*16));
        __syncthreads();

        uint32_t cxS = (tabS[k1>>1] >> ((k1&1)*16)) & 0xFFFFu;
        uint32_t cyS = (tabD[k1>>1] >> ((k1&1)*16)) & 0xFFFFu;
        uint32_t cxD = (tabD[k2>>1] >> ((k2&1)*16)) & 0xFFFFu;
        uint32_t cyD = (tabS[k2>>1] >> ((k2&1)*16)) & 0xFFFFu;
        if (k1 < 8) { cxS = 0; cyS = 0; }     // id == 0 -> invalid
        if (k2 < 8) { cxD = 0; cyD = 0; }
        g_cnt[     b*LL + tid] = cxS | (cyS << 11) | ((k1 & 7u) << 22);
        g_cnt[BL + b*LL + tid] = cxD | (cyD << 11) | ((k2 & 7u) << 22);

    } else if (bid < 81) {
        // ---------------- P/Q table section (branchless) ----------------
        float* sm   = (float*)smraw;
        float* sEW2 = sm;
        float* sW   = sm + 16384;
        float* sB   = sm + 16512;
        float* sT   = sm + 16640;
        int*   sR   = (int*)(sm + 16768);
        int bid2 = bid - 64;

        for (int i = tid; i < DD*DD; i += 1024) sEW2[i] = ew2[i];
        if (tid < DD) {
            float w = ew1[tid], b = eb1[tid];
            sW[tid] = w; sB[tid] = b;
            sT[tid] = (w != 0.0f) ? (-b / w) : __int_as_float(0x7f800000);
        }
        __syncthreads();
        if (tid < DD) {
            float td = sT[tid];
            int r = 0;
            for (int j = 0; j < DD; ++j) {
                float tj = sT[j];
                r += (tj < td || (tj == td && j < tid)) ? 1 : 0;
            }
            sR[tid] = r;
            if (bid2 == 0) g_sortedT[r] = td;
        }
        __syncthreads();

        int j  = tid >> 7;
        int dp = tid & 127;
        int k  = bid2*8 + j;
        if (k <= DD) {
            float p = 0.f, q = eb2[dp];
#pragma unroll 8
            for (int d = 0; d < DD; ++d) {
                float w = sW[d], b = sB[d];
                int   r = sR[d];
                bool act = (w > 0.f) ? (r < k) : ((w < 0.f) ? (r >= k) : (b > 0.f));
                float w2 = sEW2[d*DD + dp];
                float pm = act ? w : 0.f;
                float qm = act ? b : 0.f;
                p = fmaf(pm, w2, p);
                q = fmaf(qm, w2, q);
            }
            g_P[k*DD + dp] = p;
            g_Q[k*DD + dp] = q;
        }

    } else {
        // ---------------- g-table section ----------------
        float* sm   = (float*)smraw;
        float* sAW1 = sm;            // 1024
        float* sAB1 = sm + 1024;     // 128
        float* sW2a = sm + 1152;     // 128
        float* sW2b = sm + 1280;     // 128
        sAW1[tid] = aw1[tid];        // SS*DD == 1024 == blockDim
        if (tid < DD) {
            sAB1[tid] = ab1[tid];
            sW2a[tid] = aw2[2*tid + 0];
            sW2b[tid] = aw2[2*tid + 1];
        }
        __syncthreads();

        int idx = (bid - 81)*1024 + tid;
        if (idx < GT) {
            int s = idx / 1025;
            int c = idx - s*1025;
            float fc = (float)c;
            const float* w1r = sAW1 + s*DD;
            float a0 = 0.f, a1 = 0.f;
#pragma unroll 8
            for (int d = 0; d < DD; ++d) {
                float h = fmaxf(fmaf(fc, w1r[d], sAB1[d]), 0.f);
                a0 = fmaf(h, sW2a[d], a0);
                a1 = fmaf(h, sW2b[d], a1);
            }
            g_g[idx] = make_float2(a0, a1);
        }
    }
}

// ============================================================
// Shared element math: (s,cx,cy) -> 128-float row (lane covers 4).
// Reads the small tables from global (L2-hot).
// ============================================================
__device__ __forceinline__ float4 elem_row(int s, int cx, int cy,
                                           float ab2_0, float ab2_1, int lane) {
    float2 gx = g_g[s*1025 + cx];
    float2 gy = g_g[s*1025 + cy];
    float y0 = fmaf(0.5f, gx.x + gy.x, ab2_0);
    float y1 = fmaf(0.5f, gx.y + gy.y, ab2_1);

    float t0 = g_sortedT[lane];
    float t1 = g_sortedT[lane + 32];
    float t2 = g_sortedT[lane + 64];
    float t3 = g_sortedT[lane + 96];
    int k0 = __popc(__ballot_sync(0xffffffffu, t0 < y0))
           + __popc(__ballot_sync(0xffffffffu, t1 < y0))
           + __popc(__ballot_sync(0xffffffffu, t2 < y0))
           + __popc(__ballot_sync(0xffffffffu, t3 < y0));
    int k1 = __popc(__ballot_sync(0xffffffffu, t0 < y1))
           + __popc(__ballot_sync(0xffffffffu, t1 < y1))
           + __popc(__ballot_sync(0xffffffffu, t2 < y1))
           + __popc(__ballot_sync(0xffffffffu, t3 < y1));

    const float4* P = (const float4*)g_P;
    const float4* Q = (const float4*)g_Q;
    float4 p0 = P[k0*32 + lane], q0 = Q[k0*32 + lane];
    float4 p1 = P[k1*32 + lane], q1 = Q[k1*32 + lane];
    float4 r;
    r.x = fmaf(y0, p0.x, q0.x) + fmaf(y1, p1.x, q1.x);
    r.y = fmaf(y0, p0.y, q0.y) + fmaf(y1, p1.y, q1.y);
    r.z = fmaf(y0, p0.z, q0.z) + fmaf(y1, p1.z, q1.z);
    r.w = fmaf(y0, p0.w, q0.w) + fmaf(y1, p1.w, q1.w);
    return r;
}

// ============================================================
// Main kernel: builds its own hot table (s, cx<4, cy<4) in smem,
// then pure gather-copy; rare counts computed inline.
// ============================================================
__global__ __launch_bounds__(1024, 2)
void k_main(const float* __restrict__ ab2, float4* __restrict__ out) {
    extern __shared__ float4 sC[];      // 128 rows * 32 float4 = 64KB
    int tid = threadIdx.x;
    int lane = tid & 31;
    int wid = tid >> 5;
    float ab2_0 = __ldg(&ab2[0]), ab2_1 = __ldg(&ab2[1]);

    // build hot table: row ce = s*16 + cx*4 + cy, warp computes 4 rows
#pragma unroll
    for (int r = 0; r < 4; ++r) {
        int ce = wid*4 + r;              // 0..127
        int s  = ce >> 4;
        int cx = (ce >> 2) & 3;
        int cy = ce & 3;
        sC[ce*32 + lane] = elem_row(s, cx, cy, ab2_0, ab2_1, lane);
    }
    __syncthreads();

    const int W = 296*32;
    int e = blockIdx.x*32 + wid;
    uint32_t pk = (e < NELEM) ? g_cnt[e] : 0;
    while (e < NELEM) {
        int en = e + W;
        uint32_t pkn = (en < NELEM) ? g_cnt[en] : 0;

        int cx = pk & 0x7FF;
        int cy = (pk >> 11) & 0x7FF;
        int s  = pk >> 22;
        float4 r;
        if ((cx | cy) < 4) {
            r = sC[((s << 4) | (cx << 2) | cy)*32 + lane];
        } else {
            cx = min(cx, 1024); cy = min(cy, 1024);
            r = elem_row(s, cx, cy, ab2_0, ab2_1, lane);
        }
        out[e*32 + lane] = r;

        e = en; pk = pkn;
    }
}

// ============================================================
extern "C" void kernel_launch(void* const* d_in, const int* in_sizes, int n_in,
                              void* d_out, int out_size) {
    const int*   sid = (const int*)d_in[0];
    const int*   did = (const int*)d_in[1];
    const int*   ssn = (const int*)d_in[2];
    const int*   dsn = (const int*)d_in[3];
    const float* aw1 = (const float*)d_in[5];
    const float* ab1 = (const float*)d_in[6];
    const float* aw2 = (const float*)d_in[7];
    const float* ab2 = (const float*)d_in[8];
    const float* ew1 = (const float*)d_in[9];
    const float* eb1 = (const float*)d_in[10];
    const float* ew2 = (const float*)d_in[11];
    const float* eb2 = (const float*)d_in[12];
    float4* out = (float4*)d_out;

    size_t fusedSmem = (size_t)KEYSPACE * sizeof(uint32_t);   // 128 KB
    size_t mainSmem  = 128*32*sizeof(float4);                 // 64 KB
    cudaFuncSetAttribute(k_fused, cudaFuncAttributeMaxDynamicSharedMemorySize, (int)fusedSmem);
    cudaFuncSetAttribute(k_main,  cudaFuncAttributeMaxDynamicSharedMemorySize, (int)mainSmem);

    k_fused<<<90, 1024, fusedSmem>>>(sid, did, ssn, dsn,
                                     aw1, ab1, aw2, ew1, eb1, ew2, eb2);
    k_main<<<296, 1024, mainSmem>>>(ab2, out);
}

// round 8
// speedup vs baseline: 2.6623x; 1.0691x over previous
#include <cuda_runtime.h>
#include <cstdint>

#define BB 64
#define LL 1024
#define SS 8
#define DD 128
#define BL (BB*LL)          // 65536
#define NELEM (2*BL)        // 131072 element-sides
#define NK (DD+1)           // 129 relu-interval table rows
#define KEYSPACE 32768      // id*8 + (snap-1)
#define GT (SS*1025)        // g-table entries (s, count 0..1024)

// ---- device scratch ----
__device__ float    g_sortedT[DD];
__device__ float    g_P[NK*DD];
__device__ float    g_Q[NK*DD];        // includes folded eb2
__device__ float2   g_g[GT];           // agg-MLP lookup per (s, count)
__device__ uint32_t g_cnt[NELEM];      // packed: cx | cy<<11 | s<<22
__device__ float4   g_hot[128*32];     // hot joint table (s<8, cx<4, cy<4), 64KB

// ============================================================
// Fused prologue + count kernel. Block roles by blockIdx.x:
//   [0,64)    : per-batch histogram count        (128KB smem)
//   [64,81)   : P/Q interval tables, 8 k per blk
//   [81,90)   : agg-MLP g-table, thread per (s,c)
// ============================================================
__global__ __launch_bounds__(1024, 1)
void k_fused(const int* __restrict__ sid, const int* __restrict__ did,
             const int* __restrict__ ssn, const int* __restrict__ dsn,
             const float* __restrict__ aw1, const float* __restrict__ ab1,
             const float* __restrict__ aw2,
             const float* __restrict__ ew1, const float* __restrict__ eb1,
             const float* __restrict__ ew2, const float* __restrict__ eb2) {
    extern __shared__ uint32_t smraw[];
    int bid = blockIdx.x;
    int tid = threadIdx.x;

    if (bid < 64) {
        // ---------------- count section ----------------
        uint32_t* tabS = smraw;
        uint32_t* tabD = smraw + KEYSPACE/2;
        int b = bid;
        uint4* z = (uint4*)smraw;
#pragma unroll
        for (int i = 0; i < 8; ++i) z[tid + i*1024] = make_uint4(0,0,0,0);
        __syncthreads();

        int i = b*LL + tid;
        unsigned k1 = (unsigned)(sid[i]*8 + (ssn[i]-1));
        unsigned k2 = (unsigned)(did[i]*8 + (dsn[i]-1));
        k1 = min(k1, (unsigned)(KEYSPACE-1));
        k2 = min(k2, (unsigned)(KEYSPACE-1));
        atomicAdd(&tabS[k1>>1], 1u << ((k1&1)*16));
        atomicAdd(&tabD[k2>>1], 1u << ((k2&1)*16));
        __syncthreads();

        uint32_t cxS = (tabS[k1>>1] >> ((k1&1)*16)) & 0xFFFFu;
        uint32_t cyS = (tabD[k1>>1] >> ((k1&1)*16)) & 0xFFFFu;
        uint32_t cxD = (tabD[k2>>1] >> ((k2&1)*16)) & 0xFFFFu;
        uint32_t cyD = (tabS[k2>>1] >> ((k2&1)*16)) & 0xFFFFu;
        if (k1 < 8) { cxS = 0; cyS = 0; }     // id == 0 -> invalid
        if (k2 < 8) { cxD = 0; cyD = 0; }
        g_cnt[     b*LL + tid] = cxS | (cyS << 11) | ((k1 & 7u) << 22);
        g_cnt[BL + b*LL + tid] = cxD | (cyD << 11) | ((k2 & 7u) << 22);

    } else if (bid < 81) {
        // ---------------- P/Q table section (branchless) ----------------
        float* sm   = (float*)smraw;
        float* sEW2 = sm;
        float* sW   = sm + 16384;
        float* sB   = sm + 16512;
        float* sT   = sm + 16640;
        int*   sR   = (int*)(sm + 16768);
        int bid2 = bid - 64;

        for (int i = tid; i < DD*DD; i += 1024) sEW2[i] = ew2[i];
        if (tid < DD) {
            float w = ew1[tid], b = eb1[tid];
            sW[tid] = w; sB[tid] = b;
            sT[tid] = (w != 0.0f) ? (-b / w) : __int_as_float(0x7f800000);
        }
        __syncthreads();
        if (tid < DD) {
            float td = sT[tid];
            int r = 0;
            for (int j = 0; j < DD; ++j) {
                float tj = sT[j];
                r += (tj < td || (tj == td && j < tid)) ? 1 : 0;
            }
            sR[tid] = r;
            if (bid2 == 0) g_sortedT[r] = td;
        }
        __syncthreads();

        int j  = tid >> 7;
        int dp = tid & 127;
        int k  = bid2*8 + j;
        if (k <= DD) {
            float p = 0.f, q = eb2[dp];
#pragma unroll 8
            for (int d = 0; d < DD; ++d) {
                float w = sW[d], b = sB[d];
                int   r = sR[d];
                bool act = (w > 0.f) ? (r < k) : ((w < 0.f) ? (r >= k) : (b > 0.f));
                float w2 = sEW2[d*DD + dp];
                float pm = act ? w : 0.f;
                float qm = act ? b : 0.f;
                p = fmaf(pm, w2, p);
                q = fmaf(qm, w2, q);
            }
            g_P[k*DD + dp] = p;
            g_Q[k*DD + dp] = q;
        }

    } else {
        // ---------------- g-table section ----------------
        float* sm   = (float*)smraw;
        float* sAW1 = sm;            // 1024
        float* sAB1 = sm + 1024;     // 128
        float* sW2a = sm + 1152;     // 128
        float* sW2b = sm + 1280;     // 128
        sAW1[tid] = aw1[tid];        // SS*DD == 1024 == blockDim
        if (tid < DD) {
            sAB1[tid] = ab1[tid];
            sW2a[tid] = aw2[2*tid + 0];
            sW2b[tid] = aw2[2*tid + 1];
        }
        __syncthreads();

        int idx = (bid - 81)*1024 + tid;
        if (idx < GT) {
            int s = idx / 1025;
            int c = idx - s*1025;
            float fc = (float)c;
            const float* w1r = sAW1 + s*DD;
            float a0 = 0.f, a1 = 0.f;
#pragma unroll 8
            for (int d = 0; d < DD; ++d) {
                float h = fmaxf(fmaf(fc, w1r[d], sAB1[d]), 0.f);
                a0 = fmaf(h, sW2a[d], a0);
                a1 = fmaf(h, sW2b[d], a1);
            }
            g_g[idx] = make_float2(a0, a1);
        }
    }
}

// ============================================================
// Shared element math: (s,cx,cy) -> 128-float row (lane covers 4).
// ============================================================
__device__ __forceinline__ float4 elem_row(int s, int cx, int cy,
                                           float ab2_0, float ab2_1, int lane) {
    float2 gx = g_g[s*1025 + cx];
    float2 gy = g_g[s*1025 + cy];
    float y0 = fmaf(0.5f, gx.x + gy.x, ab2_0);
    float y1 = fmaf(0.5f, gx.y + gy.y, ab2_1);

    float t0 = g_sortedT[lane];
    float t1 = g_sortedT[lane + 32];
    float t2 = g_sortedT[lane + 64];
    float t3 = g_sortedT[lane + 96];
    int k0 = __popc(__ballot_sync(0xffffffffu, t0 < y0))
           + __popc(__ballot_sync(0xffffffffu, t1 < y0))
           + __popc(__ballot_sync(0xffffffffu, t2 < y0))
           + __popc(__ballot_sync(0xffffffffu, t3 < y0));
    int k1 = __popc(__ballot_sync(0xffffffffu, t0 < y1))
           + __popc(__ballot_sync(0xffffffffu, t1 < y1))
           + __popc(__ballot_sync(0xffffffffu, t2 < y1))
           + __popc(__ballot_sync(0xffffffffu, t3 < y1));

    const float4* P = (const float4*)g_P;
    const float4* Q = (const float4*)g_Q;
    float4 p0 = P[k0*32 + lane], q0 = Q[k0*32 + lane];
    float4 p1 = P[k1*32 + lane], q1 = Q[k1*32 + lane];
    float4 r;
    r.x = fmaf(y0, p0.x, q0.x) + fmaf(y1, p1.x, q1.x);
    r.y = fmaf(y0, p0.y, q0.y) + fmaf(y1, p1.y, q1.y);
    r.z = fmaf(y0, p0.z, q0.z) + fmaf(y1, p1.z, q1.z);
    r.w = fmaf(y0, p0.w, q0.w) + fmaf(y1, p1.w, q1.w);
    return r;
}

// ============================================================
// Hot-table generator: 128 warps, one row each.
// ============================================================
__global__ __launch_bounds__(1024, 1)
void k_hot(const float* __restrict__ ab2) {
    int wid = threadIdx.x >> 5, lane = threadIdx.x & 31;
    int ce = blockIdx.x*32 + wid;        // 0..127 (grid 4)
    int s  = ce >> 4;
    int cx = (ce >> 2) & 3;
    int cy = ce & 3;
    g_hot[ce*32 + lane] = elem_row(s, cx, cy, __ldg(&ab2[0]), __ldg(&ab2[1]), lane);
}

// ============================================================
// Main kernel: chunk-of-32 per warp. Coalesced pk load, one hotness
// ballot per chunk, fully-unrolled L1-cached gather + coalesced store.
// ============================================================
__global__ __launch_bounds__(256, 4)
void k_main(const float* __restrict__ ab2, float4* __restrict__ out) {
    int wid  = threadIdx.x >> 5;
    int lane = threadIdx.x & 31;
    int chunk = blockIdx.x*8 + wid;          // 0..4095 (grid 512)
    int base  = chunk << 5;                  // element base

    uint32_t pk = g_cnt[base + lane];        // coalesced, 1 transaction/warp
    int cx = pk & 0x7FF;
    int cy = (pk >> 11) & 0x7FF;
    int s  = pk >> 22;
    bool hot = ((cx | cy) < 4);
    int idx = (s << 4) | (cx << 2) | cy;     // valid when hot
    unsigned hm = __ballot_sync(0xffffffffu, hot);

    if (hm == 0xffffffffu) {
#pragma unroll
        for (int i = 0; i < 32; ++i) {
            int id_i = __shfl_sync(0xffffffffu, idx, i);
            out[(size_t)(base + i)*32 + lane] = g_hot[id_i*32 + lane];
        }
    } else {
        float a0 = __ldg(&ab2[0]), a1 = __ldg(&ab2[1]);
        for (int i = 0; i < 32; ++i) {
            if ((hm >> i) & 1) {
                int id_i = __shfl_sync(0xffffffffu, idx, i);
                out[(size_t)(base + i)*32 + lane] = g_hot[id_i*32 + lane];
            } else {
                int si  = __shfl_sync(0xffffffffu, s, i);
                int cxi = min(__shfl_sync(0xffffffffu, cx, i), 1024);
                int cyi = min(__shfl_sync(0xffffffffu, cy, i), 1024);
                out[(size_t)(base + i)*32 + lane] = elem_row(si, cxi, cyi, a0, a1, lane);
            }
        }
    }
}

// ============================================================
extern "C" void kernel_launch(void* const* d_in, const int* in_sizes, int n_in,
                              void* d_out, int out_size) {
    const int*   sid = (const int*)d_in[0];
    const int*   did = (const int*)d_in[1];
    const int*   ssn = (const int*)d_in[2];
    const int*   dsn = (const int*)d_in[3];
    const float* aw1 = (const float*)d_in[5];
    const float* ab1 = (const float*)d_in[6];
    const float* aw2 = (const float*)d_in[7];
    const float* ab2 = (const float*)d_in[8];
    const float* ew1 = (const float*)d_in[9];
    const float* eb1 = (const float*)d_in[10];
    const float* ew2 = (const float*)d_in[11];
    const float* eb2 = (const float*)d_in[12];
    float4* out = (float4*)d_out;

    size_t fusedSmem = (size_t)KEYSPACE * sizeof(uint32_t);   // 128 KB
    cudaFuncSetAttribute(k_fused, cudaFuncAttributeMaxDynamicSharedMemorySize, (int)fusedSmem);

    k_fused<<<90, 1024, fusedSmem>>>(sid, did, ssn, dsn,
                                     aw1, ab1, aw2, ew1, eb1, ew2, eb2);
    k_hot<<<4, 1024>>>(ab2);
    k_main<<<512, 256>>>(ab2, out);
}